// round 2
// baseline (speedup 1.0000x reference)
#include <cuda_runtime.h>
#include <math.h>

#define BATCH 2
#define SEQ   2048
#define NH    16
#define HD    64
#define HID   1024
#define F3    3072          // 3 * NH * HD
#define BS    (BATCH*SEQ)   // 4096

// ---------------- scratch (device globals; no allocation at launch time) ----
__device__ float g_qkv[(size_t)BS * F3];                 // 50.3 MB
__device__ float g_scores[(size_t)BATCH * NH * SEQ * SEQ]; // 512 MB
__device__ float g_m[BATCH * NH * SEQ];
__device__ float g_invz[BATCH * NH * SEQ];
__device__ float g_colsum[BATCH * NH * SEQ];
__device__ float g_vals[(size_t)BS * HID];               // 16.8 MB

// ---------------- generic fp32 SGEMM: 128x128 block, 8x8 microtile ---------
#define BM 128
#define BN 128
#define BKT 16
#define TM 8
#define TN 8

// C[m,n] = alpha * sum_k A[m,k] * B(k,n)
// TB=false: B is K x N row-major (B[k*ldb + n])
// TB=true : B is N x K row-major (B[n*ldb + k])   (i.e. C = A * B^T)
// batch offsets: for blockIdx.z = bz, b = bz/hdiv, h = bz%hdiv
template <bool TB>
__global__ __launch_bounds__(256, 2) void sgemm_kernel(
    const float* __restrict__ A, const float* __restrict__ B, float* __restrict__ C,
    int K, int lda, int ldb, int ldc,
    int hdiv, long sAb, long sAh, long sBb, long sBh, long sCb, long sCh,
    float alpha)
{
    __shared__ float As[BKT][BM + 4];
    __shared__ float Bs[BKT][BN + 4];

    int bz = blockIdx.z;
    int bb = bz / hdiv, hh = bz % hdiv;
    A += (long)bb * sAb + (long)hh * sAh;
    B += (long)bb * sBb + (long)hh * sBh;
    C += (long)bb * sCb + (long)hh * sCh;

    int bm0 = blockIdx.y * BM;
    int bn0 = blockIdx.x * BN;
    int tid = threadIdx.x;
    int ty = tid >> 4, tx = tid & 15;
    int ra = ty * TM;        // 0..120 step 8 (16 groups)
    int rb = tx * TN;        // 0..120 step 8

    // A-load mapping: 64 rows x 16 k per pass, 2 passes
    int am = tid >> 2;            // 0..63
    int ak = (tid & 3) * 4;       // 0,4,8,12

    float acc[TM][TN];
#pragma unroll
    for (int i = 0; i < TM; i++)
#pragma unroll
        for (int j = 0; j < TN; j++) acc[i][j] = 0.f;

    for (int t = 0; t < K; t += BKT) {
        // ---- load A tile (transpose into As[k][m]) ----
#pragma unroll
        for (int r = 0; r < 2; r++) {
            int m = am + r * 64;
            float4 v = *(const float4*)(A + (long)(bm0 + m) * lda + t + ak);
            As[ak + 0][m] = v.x; As[ak + 1][m] = v.y;
            As[ak + 2][m] = v.z; As[ak + 3][m] = v.w;
        }
        // ---- load B tile into Bs[k][n] ----
        if (!TB) {
            int n4 = (tid & 31) * 4;
            int kb = tid >> 5;           // 0..7
#pragma unroll
            for (int r = 0; r < 2; r++) {
                int k = kb + r * 8;
                float4 v = *(const float4*)(B + (long)(t + k) * ldb + bn0 + n4);
                Bs[k][n4 + 0] = v.x; Bs[k][n4 + 1] = v.y;
                Bs[k][n4 + 2] = v.z; Bs[k][n4 + 3] = v.w;
            }
        } else {
            int n = tid >> 1;            // 0..127
            int kb4 = (tid & 1) * 8;     // 0 or 8
#pragma unroll
            for (int r = 0; r < 2; r++) {
                int k = kb4 + r * 4;     // 0,4 or 8,12
                float4 v = *(const float4*)(B + (long)(bn0 + n) * ldb + t + k);
                Bs[k + 0][n] = v.x; Bs[k + 1][n] = v.y;
                Bs[k + 2][n] = v.z; Bs[k + 3][n] = v.w;
            }
        }
        __syncthreads();

#pragma unroll
        for (int kk = 0; kk < BKT; kk++) {
            float a[TM], b[TN];
            *(float4*)&a[0] = *(const float4*)&As[kk][ra];
            *(float4*)&a[4] = *(const float4*)&As[kk][ra + 4];
            *(float4*)&b[0] = *(const float4*)&Bs[kk][rb];
            *(float4*)&b[4] = *(const float4*)&Bs[kk][rb + 4];
#pragma unroll
            for (int i = 0; i < TM; i++)
#pragma unroll
                for (int j = 0; j < TN; j++) acc[i][j] += a[i] * b[j];
        }
        __syncthreads();
    }

#pragma unroll
    for (int i = 0; i < TM; i++) {
        long row = bm0 + ra + i;
#pragma unroll
        for (int j = 0; j < TN; j += 4) {
            float4 v;
            v.x = alpha * acc[i][j + 0];
            v.y = alpha * acc[i][j + 1];
            v.z = alpha * acc[i][j + 2];
            v.w = alpha * acc[i][j + 3];
            *(float4*)(C + row * ldc + bn0 + rb + j) = v;
        }
    }
}

// ---------------- softmax row stats: max + 1/sum(exp) per q-row ------------
__global__ void rowstats_kernel(const float* __restrict__ Sc,
                                float* __restrict__ Mout, float* __restrict__ IZout)
{
    long row = blockIdx.x;
    const float* p = Sc + row * (long)SEQ;
    int tid = threadIdx.x;   // 256
    __shared__ float red[256];

    float m = -1e30f;
    for (int k = tid; k < SEQ; k += 256) m = fmaxf(m, p[k]);
    red[tid] = m; __syncthreads();
    for (int off = 128; off > 0; off >>= 1) {
        if (tid < off) red[tid] = fmaxf(red[tid], red[tid + off]);
        __syncthreads();
    }
    m = red[0]; __syncthreads();

    float z = 0.f;
    for (int k = tid; k < SEQ; k += 256) z += __expf(p[k] - m);
    red[tid] = z; __syncthreads();
    for (int off = 128; off > 0; off >>= 1) {
        if (tid < off) red[tid] += red[tid + off];
        __syncthreads();
    }
    if (tid == 0) { Mout[row] = m; IZout[row] = 1.0f / red[0]; }
}

// ---------------- zero colsum ----------------------------------------------
__global__ void zero_colsum_kernel(float* __restrict__ cs)
{
    int i = blockIdx.x * 256 + threadIdx.x;
    if (i < BATCH * NH * SEQ) cs[i] = 0.f;
}

// ---------------- colsum: sum over q of normalized softmax -----------------
// grid: (16 qchunks, 32 heads), 256 threads
__global__ void colsum_kernel(const float* __restrict__ Sc,
                              const float* __restrict__ M, const float* __restrict__ IZ,
                              float* __restrict__ cs)
{
    int bh = blockIdx.y;
    int q0 = blockIdx.x * 128;
    int tid = threadIdx.x;
    const float* Sp = Sc + (long)bh * SEQ * SEQ;
    __shared__ float sm[128], siz[128];

    if (tid < 128) {
        sm[tid]  = M[(long)bh * SEQ + q0 + tid];
        siz[tid] = IZ[(long)bh * SEQ + q0 + tid];
    }
    __syncthreads();

    float acc[8];
#pragma unroll
    for (int j = 0; j < 8; j++) acc[j] = 0.f;

    for (int q = 0; q < 128; q++) {
        const float* rowp = Sp + (long)(q0 + q) * SEQ;
        float mq = sm[q], iz = siz[q];
#pragma unroll
        for (int j = 0; j < 8; j++) {
            float s = rowp[tid + j * 256];
            acc[j] += __expf(s - mq) * iz;
        }
    }
#pragma unroll
    for (int j = 0; j < 8; j++)
        atomicAdd(&cs[(long)bh * SEQ + tid + j * 256], acc[j]);
}

// ---------------- scale V rows by colsum -----------------------------------
__global__ void scale_v_kernel(const float* __restrict__ qkv,
                               const float* __restrict__ cs,
                               float* __restrict__ vals)
{
    long i = (long)blockIdx.x * 256 + threadIdx.x;   // over BS*HID
    int f  = (int)(i & (HID - 1));
    long bs = i >> 10;
    int h  = f >> 6;
    int b  = (int)(bs >> 11);
    int s  = (int)(bs & (SEQ - 1));
    float v = qkv[bs * F3 + 2 * HID + f];
    vals[i] = v * cs[((long)b * NH + h) * SEQ + s];
}

// ---------------- launcher --------------------------------------------------
extern "C" void kernel_launch(void* const* d_in, const int* in_sizes, int n_in,
                              void* d_out, int out_size)
{
    const float* x     = (const float*)d_in[0];
    const float* w_qkv = (const float*)d_in[1];
    const float* w_o   = (const float*)d_in[2];
    float* out = (float*)d_out;

    float *p_qkv, *p_sc, *p_m, *p_iz, *p_cs, *p_vals;
    cudaGetSymbolAddress((void**)&p_qkv,  g_qkv);
    cudaGetSymbolAddress((void**)&p_sc,   g_scores);
    cudaGetSymbolAddress((void**)&p_m,    g_m);
    cudaGetSymbolAddress((void**)&p_iz,   g_invz);
    cudaGetSymbolAddress((void**)&p_cs,   g_colsum);
    cudaGetSymbolAddress((void**)&p_vals, g_vals);

    dim3 blk(256);

    // 0. zero colsum accumulators
    zero_colsum_kernel<<<(BATCH * NH * SEQ + 255) / 256, blk>>>(p_cs);

    // 1. qkv = x @ w_qkv   [4096,1024]x[1024,3072]
    sgemm_kernel<false><<<dim3(F3 / BN, BS / BM, 1), blk>>>(
        x, w_qkv, p_qkv, HID, HID, F3, F3,
        1, 0, 0, 0, 0, 0, 0, 1.0f);

    // 2. scores = Q @ K^T / 8 per (b,h)   [2048,64]x[2048,64]^T, 32 batches
    sgemm_kernel<true><<<dim3(SEQ / BN, SEQ / BM, BATCH * NH), blk>>>(
        p_qkv, p_qkv + HID, p_sc, HD, F3, F3, SEQ,
        NH,
        (long)SEQ * F3, (long)HD,          // A (Q) offsets per b, h
        (long)SEQ * F3, (long)HD,          // B (K) offsets per b, h
        (long)NH * SEQ * SEQ, (long)SEQ * SEQ,  // C offsets
        0.125f);

    // 3. per-q-row softmax stats
    rowstats_kernel<<<BATCH * NH * SEQ, blk>>>(p_sc, p_m, p_iz);

    // 4. colsum[b,h,k] = sum_q softmax(scores)[q,k]
    colsum_kernel<<<dim3(SEQ / 128, BATCH * NH), blk>>>(p_sc, p_m, p_iz, p_cs);

    // 5. values = v * colsum (elementwise, reshaped to [BS, HID])
    scale_v_kernel<<<(int)(((long)BS * HID) / 256), blk>>>(p_qkv, p_cs, p_vals);

    // 6. out = values @ w_o   [4096,1024]x[1024,1024]
    sgemm_kernel<false><<<dim3(HID / BN, BS / BM, 1), blk>>>(
        p_vals, w_o, out, HID, HID, HID, HID,
        1, 0, 0, 0, 0, 0, 0, 1.0f);
}

// round 3
// speedup vs baseline: 2.3314x; 2.3314x over previous
#include <cuda_runtime.h>
#include <math.h>

#define BATCH 2
#define SEQ   2048
#define NH    16
#define HD    64
#define HID   1024
#define F3    3072
#define BS    (BATCH*SEQ)
#define NBH   (BATCH*NH)        // 32
#define KT    (SEQ/128)         // 16 k-tiles per row

// ---------------- scratch (device globals) ---------------------------------
__device__ float g_qkv[(size_t)BS * F3];                 // 50.3 MB
__device__ float g_vals[(size_t)BS * HID];               // 16.8 MB
__device__ float g_m[NBH * SEQ];                         // final row max
__device__ float g_invz[NBH * SEQ];                      // final 1/z
__device__ float g_colsum[NBH * SEQ];
__device__ float g_mp[(size_t)NBH * SEQ * KT];           // partial max   (4 MB)
__device__ float g_zp[(size_t)NBH * SEQ * KT];           // partial sumexp(4 MB)

__device__ __forceinline__ unsigned f2t(float f) {
    unsigned u; asm("cvt.rna.tf32.f32 %0, %1;" : "=r"(u) : "f"(f)); return u;
}

__device__ __forceinline__ void mma_tf32(float* c, const unsigned* a, const unsigned* b) {
    asm volatile(
        "mma.sync.aligned.m16n8k8.row.col.f32.tf32.tf32.f32 "
        "{%0,%1,%2,%3}, {%4,%5,%6,%7}, {%8,%9}, {%0,%1,%2,%3};"
        : "+f"(c[0]), "+f"(c[1]), "+f"(c[2]), "+f"(c[3])
        : "r"(a[0]), "r"(a[1]), "r"(a[2]), "r"(a[3]), "r"(b[0]), "r"(b[1]));
}

// ---------------- tf32 tensor-core GEMM, 128x128 tile, 8 warps -------------
// MODE 0: C = alpha * A*B(^T)            (plain write)
// MODE 1: no C; per-row-tile softmax partials (max, sumexp) -> Mp, Zp
// MODE 2: no C; colsum += sum_q exp(alpha*s - Mf[q]) * IZf[q]
template <bool TB, int MODE>
__global__ __launch_bounds__(256, 2) void mma_gemm(
    const float* __restrict__ A, const float* __restrict__ B, float* __restrict__ C,
    int K, int lda, int ldb, int ldc,
    int hdiv, long sAb, long sAh, long sBb, long sBh, long sCb, long sCh,
    float alpha,
    const float* __restrict__ Mf, const float* __restrict__ IZf,
    float* __restrict__ Mp, float* __restrict__ Zp,
    float* __restrict__ colsum)
{
    __shared__ unsigned As[128][20];       // row-major A tile [m][k], pad->20
    __shared__ unsigned Bs[2560];          // TB=0: [k][n] 16x136 ; TB=1: [n][k] 128x20
    __shared__ float s_red[8][128];

    const int tid  = threadIdx.x;
    const int lane = tid & 31, wid = tid >> 5;
    const int wm = wid & 1, wn = wid >> 1;         // warp tile 64x32
    const int qr = lane >> 2, qc = lane & 3;
    const int bz = blockIdx.z;
    const int bb = bz / hdiv, hh = bz % hdiv;
    A += (long)bb * sAb + (long)hh * sAh;
    B += (long)bb * sBb + (long)hh * sBh;
    if (MODE == 0) C += (long)bb * sCb + (long)hh * sCh;
    const int bm0 = blockIdx.y * 128, bn0 = blockIdx.x * 128;

    if (MODE == 2) {                 // preload final row stats for this q-block
        if (tid < 128) {
            long r = (long)bz * SEQ + bm0 + tid;
            s_red[0][tid] = Mf[r];
            s_red[1][tid] = IZf[r];
        }
    }

    float acc[4][4][4];
#pragma unroll
    for (int i = 0; i < 4; i++)
#pragma unroll
        for (int j = 0; j < 4; j++)
#pragma unroll
            for (int f = 0; f < 4; f++) acc[i][j][f] = 0.f;

    const int am = tid >> 2, ak = (tid & 3) * 4;
    const int nbF = (tid & 31) * 4, kbF = tid >> 5;
    const int nbT = tid >> 1, kbT = (tid & 1) * 8;

    for (int t = 0; t < K; t += 16) {
        // A tile -> As[m][k]
#pragma unroll
        for (int r = 0; r < 2; r++) {
            int m = am + r * 64;
            float4 v = *(const float4*)(A + (long)(bm0 + m) * lda + t + ak);
            uint4 u = make_uint4(f2t(v.x), f2t(v.y), f2t(v.z), f2t(v.w));
            *(uint4*)&As[m][ak] = u;
        }
        // B tile
        if (!TB) {
#pragma unroll
            for (int r = 0; r < 2; r++) {
                int k = kbF + r * 8;
                float4 v = *(const float4*)(B + (long)(t + k) * ldb + bn0 + nbF);
                uint4 u = make_uint4(f2t(v.x), f2t(v.y), f2t(v.z), f2t(v.w));
                *(uint4*)&Bs[k * 136 + nbF] = u;
            }
        } else {
#pragma unroll
            for (int r = 0; r < 2; r++) {
                int k = kbT + r * 4;
                float4 v = *(const float4*)(B + (long)(bn0 + nbT) * ldb + t + k);
                uint4 u = make_uint4(f2t(v.x), f2t(v.y), f2t(v.z), f2t(v.w));
                *(uint4*)&Bs[nbT * 20 + k] = u;
            }
        }
        __syncthreads();

#pragma unroll
        for (int ks = 0; ks < 16; ks += 8) {
            unsigned a[4][4], bf[4][2];
#pragma unroll
            for (int i = 0; i < 4; i++) {
                int mr = wm * 64 + i * 16 + qr;
                a[i][0] = As[mr][ks + qc];
                a[i][1] = As[mr + 8][ks + qc];
                a[i][2] = As[mr][ks + 4 + qc];
                a[i][3] = As[mr + 8][ks + 4 + qc];
            }
#pragma unroll
            for (int j = 0; j < 4; j++) {
                int nc = wn * 32 + j * 8 + qr;
                if (!TB) {
                    bf[j][0] = Bs[(ks + qc) * 136 + nc];
                    bf[j][1] = Bs[(ks + 4 + qc) * 136 + nc];
                } else {
                    bf[j][0] = Bs[nc * 20 + ks + qc];
                    bf[j][1] = Bs[nc * 20 + ks + 4 + qc];
                }
            }
#pragma unroll
            for (int i = 0; i < 4; i++)
#pragma unroll
                for (int j = 0; j < 4; j++) mma_tf32(acc[i][j], a[i], bf[j]);
        }
        __syncthreads();
    }

    // ---------------- epilogues ----------------
    if (MODE == 0) {
#pragma unroll
        for (int i = 0; i < 4; i++) {
            long row = bm0 + wm * 64 + i * 16 + qr;
#pragma unroll
            for (int j = 0; j < 4; j++) {
                int col = bn0 + wn * 32 + j * 8 + 2 * qc;
                float2 v0 = make_float2(alpha * acc[i][j][0], alpha * acc[i][j][1]);
                float2 v1 = make_float2(alpha * acc[i][j][2], alpha * acc[i][j][3]);
                *(float2*)(C + row * ldc + col) = v0;
                *(float2*)(C + (row + 8) * ldc + col) = v1;
            }
        }
    }

    if (MODE == 1) {
        float lm[4][2];
#pragma unroll
        for (int i = 0; i < 4; i++)
#pragma unroll
            for (int h = 0; h < 2; h++) {
                float m = -1e30f;
#pragma unroll
                for (int j = 0; j < 4; j++) {
                    m = fmaxf(m, acc[i][j][2 * h]);
                    m = fmaxf(m, acc[i][j][2 * h + 1]);
                }
                lm[i][h] = alpha * m;
            }
#pragma unroll
        for (int d = 1; d <= 2; d <<= 1)
#pragma unroll
            for (int i = 0; i < 4; i++)
#pragma unroll
                for (int h = 0; h < 2; h++)
                    lm[i][h] = fmaxf(lm[i][h], __shfl_xor_sync(0xffffffffu, lm[i][h], d));
        if (qc == 0)
#pragma unroll
            for (int i = 0; i < 4; i++)
#pragma unroll
                for (int h = 0; h < 2; h++)
                    s_red[wn][wm * 64 + i * 16 + h * 8 + qr] = lm[i][h];
        __syncthreads();

        float lz[4][2];
#pragma unroll
        for (int i = 0; i < 4; i++)
#pragma unroll
            for (int h = 0; h < 2; h++) {
                int lr = wm * 64 + i * 16 + h * 8 + qr;
                float fm = fmaxf(fmaxf(s_red[0][lr], s_red[1][lr]),
                                 fmaxf(s_red[2][lr], s_red[3][lr]));
                float z = 0.f;
#pragma unroll
                for (int j = 0; j < 4; j++) {
                    z += __expf(alpha * acc[i][j][2 * h]     - fm);
                    z += __expf(alpha * acc[i][j][2 * h + 1] - fm);
                }
                lz[i][h] = z;
            }
#pragma unroll
        for (int d = 1; d <= 2; d <<= 1)
#pragma unroll
            for (int i = 0; i < 4; i++)
#pragma unroll
                for (int h = 0; h < 2; h++)
                    lz[i][h] += __shfl_xor_sync(0xffffffffu, lz[i][h], d);
        if (qc == 0)
#pragma unroll
            for (int i = 0; i < 4; i++)
#pragma unroll
                for (int h = 0; h < 2; h++)
                    s_red[4 + wn][wm * 64 + i * 16 + h * 8 + qr] = lz[i][h];
        __syncthreads();

        if (tid < 128) {
            float m = fmaxf(fmaxf(s_red[0][tid], s_red[1][tid]),
                            fmaxf(s_red[2][tid], s_red[3][tid]));
            float z = s_red[4][tid] + s_red[5][tid] + s_red[6][tid] + s_red[7][tid];
            long idx = (((long)bz * SEQ + bm0 + tid) << 4) + blockIdx.x;
            Mp[idx] = m;
            Zp[idx] = z;
        }
    }

    if (MODE == 2) {
        float cs[4][2];
#pragma unroll
        for (int j = 0; j < 4; j++) { cs[j][0] = 0.f; cs[j][1] = 0.f; }
#pragma unroll
        for (int i = 0; i < 4; i++)
#pragma unroll
            for (int h = 0; h < 2; h++) {
                int lr = wm * 64 + i * 16 + h * 8 + qr;
                float m = s_red[0][lr], iz = s_red[1][lr];
#pragma unroll
                for (int j = 0; j < 4; j++) {
                    cs[j][0] += __expf(alpha * acc[i][j][2 * h]     - m) * iz;
                    cs[j][1] += __expf(alpha * acc[i][j][2 * h + 1] - m) * iz;
                }
            }
#pragma unroll
        for (int d = 4; d <= 16; d <<= 1)
#pragma unroll
            for (int j = 0; j < 4; j++) {
                cs[j][0] += __shfl_xor_sync(0xffffffffu, cs[j][0], d);
                cs[j][1] += __shfl_xor_sync(0xffffffffu, cs[j][1], d);
            }
        if (qr == 0) {
#pragma unroll
            for (int j = 0; j < 4; j++) {
                int col = bn0 + wn * 32 + j * 8 + 2 * qc;
                atomicAdd(&colsum[(long)bz * SEQ + col],     cs[j][0]);
                atomicAdd(&colsum[(long)bz * SEQ + col + 1], cs[j][1]);
            }
        }
    }
}

// ---------------- combine partials -> final (m, 1/z) -----------------------
__global__ void combine_kernel(const float* __restrict__ Mp, const float* __restrict__ Zp,
                               float* __restrict__ Mf, float* __restrict__ IZf)
{
    int row = blockIdx.x * 256 + threadIdx.x;
    if (row >= NBH * SEQ) return;
    const float* mp = Mp + (long)row * KT;
    const float* zp = Zp + (long)row * KT;
    float m = -1e30f;
#pragma unroll
    for (int t = 0; t < KT; t++) m = fmaxf(m, mp[t]);
    float z = 0.f;
#pragma unroll
    for (int t = 0; t < KT; t++) z += zp[t] * __expf(mp[t] - m);
    Mf[row] = m;
    IZf[row] = 1.0f / z;
}

// ---------------- zero colsum ----------------------------------------------
__global__ void zero_colsum_kernel(float* __restrict__ cs)
{
    int i = blockIdx.x * 256 + threadIdx.x;
    if (i < NBH * SEQ) cs[i] = 0.f;
}

// ---------------- scale V rows by colsum -----------------------------------
__global__ void scale_v_kernel(const float* __restrict__ qkv,
                               const float* __restrict__ cs,
                               float* __restrict__ vals)
{
    long i = (long)blockIdx.x * 256 + threadIdx.x;
    int f  = (int)(i & (HID - 1));
    long bs = i >> 10;
    int h  = f >> 6;
    int b  = (int)(bs >> 11);
    int s  = (int)(bs & (SEQ - 1));
    float v = qkv[bs * F3 + 2 * HID + f];
    vals[i] = v * cs[((long)b * NH + h) * SEQ + s];
}

// ---------------- launcher --------------------------------------------------
extern "C" void kernel_launch(void* const* d_in, const int* in_sizes, int n_in,
                              void* d_out, int out_size)
{
    const float* x     = (const float*)d_in[0];
    const float* w_qkv = (const float*)d_in[1];
    const float* w_o   = (const float*)d_in[2];
    float* out = (float*)d_out;

    float *p_qkv, *p_vals, *p_m, *p_iz, *p_cs, *p_mp, *p_zp;
    cudaGetSymbolAddress((void**)&p_qkv,  g_qkv);
    cudaGetSymbolAddress((void**)&p_vals, g_vals);
    cudaGetSymbolAddress((void**)&p_m,    g_m);
    cudaGetSymbolAddress((void**)&p_iz,   g_invz);
    cudaGetSymbolAddress((void**)&p_cs,   g_colsum);
    cudaGetSymbolAddress((void**)&p_mp,   g_mp);
    cudaGetSymbolAddress((void**)&p_zp,   g_zp);

    dim3 blk(256);

    // 0. zero colsum accumulators
    zero_colsum_kernel<<<(NBH * SEQ + 255) / 256, blk>>>(p_cs);

    // 1. qkv = x @ w_qkv   (tf32 tensor cores)
    mma_gemm<false, 0><<<dim3(F3 / 128, BS / 128, 1), blk>>>(
        x, w_qkv, p_qkv, HID, HID, F3, F3,
        1, 0, 0, 0, 0, 0, 0, 1.0f,
        nullptr, nullptr, nullptr, nullptr, nullptr);

    // 2. pass 1: QK^T fused row-softmax partials (no score materialization)
    mma_gemm<true, 1><<<dim3(SEQ / 128, SEQ / 128, NBH), blk>>>(
        p_qkv, p_qkv + HID, nullptr, HD, F3, F3, 0,
        NH, (long)SEQ * F3, (long)HD, (long)SEQ * F3, (long)HD, 0, 0,
        0.125f,
        nullptr, nullptr, p_mp, p_zp, nullptr);

    // 3. combine partials -> final m, 1/z per q-row
    combine_kernel<<<(NBH * SEQ + 255) / 256, blk>>>(p_mp, p_zp, p_m, p_iz);

    // 4. pass 2: QK^T recompute fused colsum accumulation
    mma_gemm<true, 2><<<dim3(SEQ / 128, SEQ / 128, NBH), blk>>>(
        p_qkv, p_qkv + HID, nullptr, HD, F3, F3, 0,
        NH, (long)SEQ * F3, (long)HD, (long)SEQ * F3, (long)HD, 0, 0,
        0.125f,
        p_m, p_iz, nullptr, nullptr, p_cs);

    // 5. values = v * colsum
    scale_v_kernel<<<(int)(((long)BS * HID) / 256), blk>>>(p_qkv, p_cs, p_vals);

    // 6. out = values @ w_o   (tf32 tensor cores)
    mma_gemm<false, 0><<<dim3(HID / 128, BS / 128, 1), blk>>>(
        p_vals, w_o, out, HID, HID, HID, HID,
        1, 0, 0, 0, 0, 0, 0, 1.0f,
        nullptr, nullptr, nullptr, nullptr, nullptr);
}

// round 4
// speedup vs baseline: 2.9379x; 1.2601x over previous
#include <cuda_runtime.h>
#include <math.h>

#define BATCH 2
#define SEQ   2048
#define NH    16
#define HD    64
#define HID   1024
#define F3    3072
#define BS    (BATCH*SEQ)
#define NBH   (BATCH*NH)        // 32

// 0.125 * log2(e)  (fold score scale into ex2)
#define C2EXP 0.1803368801111204f

// ---------------- scratch (device globals) ---------------------------------
__device__ float g_qkv[(size_t)BS * F3];                 // 50.3 MB
__device__ float g_z[NBH * SEQ];                         // row sum of exp
__device__ float g_colsum[NBH * SEQ];

__device__ __forceinline__ unsigned f2t(float f) {
    unsigned u; asm("cvt.rna.tf32.f32 %0, %1;" : "=r"(u) : "f"(f)); return u;
}
__device__ __forceinline__ float ex2f(float x) {
    float r; asm("ex2.approx.f32 %0, %1;" : "=f"(r) : "f"(x)); return r;
}
__device__ __forceinline__ void mma_tf32(float* c, const unsigned* a, const unsigned* b) {
    asm volatile(
        "mma.sync.aligned.m16n8k8.row.col.f32.tf32.tf32.f32 "
        "{%0,%1,%2,%3}, {%4,%5,%6,%7}, {%8,%9}, {%0,%1,%2,%3};"
        : "+f"(c[0]), "+f"(c[1]), "+f"(c[2]), "+f"(c[3])
        : "r"(a[0]), "r"(a[1]), "r"(a[2]), "r"(a[3]), "r"(b[0]), "r"(b[1]));
}

// ======================= generic NN GEMM, double-buffered ===================
// C[m,n] = alpha * sum_k A[m,k]*B[k,n];  SCALE: A scaled by colsum per (row, k/64)
template <bool SCALE>
__global__ __launch_bounds__(256, 2) void gemm_nn(
    const float* __restrict__ A, const float* __restrict__ B, float* __restrict__ C,
    int K, int lda, int ldb, int ldc, float alpha, const float* __restrict__ cs)
{
    __shared__ unsigned As[128][20];
    __shared__ unsigned Bs[16 * 136];

    const int tid = threadIdx.x, lane = tid & 31, wid = tid >> 5;
    const int wm = wid & 1, wn = wid >> 1, qr = lane >> 2, qc = lane & 3;
    const int bm0 = blockIdx.y * 128, bn0 = blockIdx.x * 128;
    const int am = tid >> 2, ak = (tid & 3) * 4;
    const int nb = (tid & 31) * 4, kb = tid >> 5;

    float4 rA[2], rB[2];

    auto loadAB = [&](int t) {
#pragma unroll
        for (int rr = 0; rr < 2; rr++) {
            int m = am + rr * 64;
            float4 v = *(const float4*)(A + (long)(bm0 + m) * lda + t + ak);
            if (SCALE) {
                int mg = bm0 + m;
                int b = mg >> 11, s = mg & (SEQ - 1);
                int h = (t + ak) >> 6;
                float sc = cs[(((long)b << 4) + h) * SEQ + s];
                v.x *= sc; v.y *= sc; v.z *= sc; v.w *= sc;
            }
            rA[rr] = v;
            int k = kb + rr * 8;
            rB[rr] = *(const float4*)(B + (long)(t + k) * ldb + bn0 + nb);
        }
    };
    loadAB(0);

    float acc[4][4][4];
#pragma unroll
    for (int i = 0; i < 4; i++)
#pragma unroll
        for (int j = 0; j < 4; j++)
#pragma unroll
            for (int f = 0; f < 4; f++) acc[i][j][f] = 0.f;

#pragma unroll 1
    for (int t = 0; t < K; t += 16) {
#pragma unroll
        for (int rr = 0; rr < 2; rr++) {
            int m = am + rr * 64;
            *(uint4*)&As[m][ak] =
                make_uint4(f2t(rA[rr].x), f2t(rA[rr].y), f2t(rA[rr].z), f2t(rA[rr].w));
            int k = kb + rr * 8;
            *(uint4*)&Bs[k * 136 + nb] =
                make_uint4(f2t(rB[rr].x), f2t(rB[rr].y), f2t(rB[rr].z), f2t(rB[rr].w));
        }
        __syncthreads();
        if (t + 16 < K) loadAB(t + 16);

#pragma unroll
        for (int ks = 0; ks < 16; ks += 8) {
            unsigned a[4][4], bf[4][2];
#pragma unroll
            for (int i = 0; i < 4; i++) {
                int mr = wm * 64 + i * 16 + qr;
                a[i][0] = As[mr][ks + qc];
                a[i][1] = As[mr + 8][ks + qc];
                a[i][2] = As[mr][ks + 4 + qc];
                a[i][3] = As[mr + 8][ks + 4 + qc];
            }
#pragma unroll
            for (int j = 0; j < 4; j++) {
                int nc = wn * 32 + j * 8 + qr;
                bf[j][0] = Bs[(ks + qc) * 136 + nc];
                bf[j][1] = Bs[(ks + 4 + qc) * 136 + nc];
            }
#pragma unroll
            for (int i = 0; i < 4; i++)
#pragma unroll
                for (int j = 0; j < 4; j++) mma_tf32(acc[i][j], a[i], bf[j]);
        }
        __syncthreads();
    }

#pragma unroll
    for (int i = 0; i < 4; i++) {
        long row = bm0 + wm * 64 + i * 16 + qr;
#pragma unroll
        for (int j = 0; j < 4; j++) {
            int col = bn0 + wn * 32 + j * 8 + 2 * qc;
            *(float2*)(C + row * ldc + col) =
                make_float2(alpha * acc[i][j][0], alpha * acc[i][j][1]);
            *(float2*)(C + (row + 8) * ldc + col) =
                make_float2(alpha * acc[i][j][2], alpha * acc[i][j][3]);
        }
    }
}

// ======================= specialized QK^T pass (K=64, one sync) =============
// MODE 1: Z[q] += sum_k exp(s_qk)        (row partials via atomics)
// MODE 2: colsum[k] += sum_q exp(s_qk)/Z[q]
template <int MODE>
__global__ __launch_bounds__(256, 2) void qk_kernel(
    const float* __restrict__ qkv, float* __restrict__ Z, float* __restrict__ colsum)
{
    extern __shared__ char dyn[];
    unsigned (*Qs)[68] = (unsigned(*)[68])dyn;                 // 128x68
    unsigned (*Ks)[68] = (unsigned(*)[68])(dyn + 34816);       // 128x68
    float* s_red = (float*)(dyn + 69632);                      // 4*128
    float* s_iz  = (float*)(dyn + 71680);                      // 128

    const int tid = threadIdx.x, lane = tid & 31, wid = tid >> 5;
    const int wm = wid & 1, wn = wid >> 1, qr = lane >> 2, qc = lane & 3;
    const int bz = blockIdx.z;                 // b*NH + h
    const int b = bz >> 4, h = bz & 15;
    const float* Qp = qkv + (long)b * SEQ * F3 + h * HD;
    const float* Kp = Qp + HID;
    const int bm0 = blockIdx.y * 128, bn0 = blockIdx.x * 128;

    const int lr = tid >> 4, lc = (tid & 15) * 4;
#pragma unroll
    for (int r = 0; r < 8; r++) {
        int row = lr + r * 16;
        float4 vq = *(const float4*)(Qp + (long)(bm0 + row) * F3 + lc);
        float4 vk = *(const float4*)(Kp + (long)(bn0 + row) * F3 + lc);
        *(uint4*)&Qs[row][lc] = make_uint4(f2t(vq.x), f2t(vq.y), f2t(vq.z), f2t(vq.w));
        *(uint4*)&Ks[row][lc] = make_uint4(f2t(vk.x), f2t(vk.y), f2t(vk.z), f2t(vk.w));
    }
    if (MODE == 2 && tid < 128)
        s_iz[tid] = 1.0f / Z[(long)bz * SEQ + bm0 + tid];
    __syncthreads();

    float acc[4][4][4];
#pragma unroll
    for (int i = 0; i < 4; i++)
#pragma unroll
        for (int j = 0; j < 4; j++)
#pragma unroll
            for (int f = 0; f < 4; f++) acc[i][j][f] = 0.f;

#pragma unroll
    for (int ks = 0; ks < 64; ks += 8) {
        unsigned a[4][4], bf[4][2];
#pragma unroll
        for (int i = 0; i < 4; i++) {
            int mr = wm * 64 + i * 16 + qr;
            a[i][0] = Qs[mr][ks + qc];
            a[i][1] = Qs[mr + 8][ks + qc];
            a[i][2] = Qs[mr][ks + 4 + qc];
            a[i][3] = Qs[mr + 8][ks + 4 + qc];
        }
#pragma unroll
        for (int j = 0; j < 4; j++) {
            int nc = wn * 32 + j * 8 + qr;
            bf[j][0] = Ks[nc][ks + qc];
            bf[j][1] = Ks[nc][ks + 4 + qc];
        }
#pragma unroll
        for (int i = 0; i < 4; i++)
#pragma unroll
            for (int j = 0; j < 4; j++) mma_tf32(acc[i][j], a[i], bf[j]);
    }

    if (MODE == 1) {
        float lz[4][2];
#pragma unroll
        for (int i = 0; i < 4; i++)
#pragma unroll
            for (int h2 = 0; h2 < 2; h2++) {
                float z = 0.f;
#pragma unroll
                for (int j = 0; j < 4; j++) {
                    z += ex2f(acc[i][j][2 * h2]     * C2EXP);
                    z += ex2f(acc[i][j][2 * h2 + 1] * C2EXP);
                }
                lz[i][h2] = z;
            }
#pragma unroll
        for (int d = 1; d <= 2; d <<= 1)
#pragma unroll
            for (int i = 0; i < 4; i++)
#pragma unroll
                for (int h2 = 0; h2 < 2; h2++)
                    lz[i][h2] += __shfl_xor_sync(0xffffffffu, lz[i][h2], d);
        if (qc == 0)
#pragma unroll
            for (int i = 0; i < 4; i++)
#pragma unroll
                for (int h2 = 0; h2 < 2; h2++)
                    s_red[wn * 128 + wm * 64 + i * 16 + h2 * 8 + qr] = lz[i][h2];
        __syncthreads();
        if (tid < 128) {
            float z = s_red[tid] + s_red[128 + tid] + s_red[256 + tid] + s_red[384 + tid];
            atomicAdd(&Z[(long)bz * SEQ + bm0 + tid], z);
        }
    }

    if (MODE == 2) {
        float cs[4][2];
#pragma unroll
        for (int j = 0; j < 4; j++) { cs[j][0] = 0.f; cs[j][1] = 0.f; }
#pragma unroll
        for (int i = 0; i < 4; i++)
#pragma unroll
            for (int h2 = 0; h2 < 2; h2++) {
                float iz = s_iz[wm * 64 + i * 16 + h2 * 8 + qr];
#pragma unroll
                for (int j = 0; j < 4; j++) {
                    cs[j][0] += ex2f(acc[i][j][2 * h2]     * C2EXP) * iz;
                    cs[j][1] += ex2f(acc[i][j][2 * h2 + 1] * C2EXP) * iz;
                }
            }
#pragma unroll
        for (int d = 4; d <= 16; d <<= 1)
#pragma unroll
            for (int j = 0; j < 4; j++) {
                cs[j][0] += __shfl_xor_sync(0xffffffffu, cs[j][0], d);
                cs[j][1] += __shfl_xor_sync(0xffffffffu, cs[j][1], d);
            }
        if (qr == 0) {
#pragma unroll
            for (int j = 0; j < 4; j++) {
                int col = bn0 + wn * 32 + j * 8 + 2 * qc;
                atomicAdd(&colsum[(long)bz * SEQ + col],     cs[j][0]);
                atomicAdd(&colsum[(long)bz * SEQ + col + 1], cs[j][1]);
            }
        }
    }
}

// ---------------- zero accumulators ----------------------------------------
__global__ void zero_kernel(float* __restrict__ z, float* __restrict__ cs)
{
    int i = blockIdx.x * 256 + threadIdx.x;
    if (i < NBH * SEQ) { z[i] = 0.f; cs[i] = 0.f; }
}

// ---------------- launcher --------------------------------------------------
#define QK_SMEM 72192

extern "C" void kernel_launch(void* const* d_in, const int* in_sizes, int n_in,
                              void* d_out, int out_size)
{
    const float* x     = (const float*)d_in[0];
    const float* w_qkv = (const float*)d_in[1];
    const float* w_o   = (const float*)d_in[2];
    float* out = (float*)d_out;

    float *p_qkv, *p_z, *p_cs;
    cudaGetSymbolAddress((void**)&p_qkv, g_qkv);
    cudaGetSymbolAddress((void**)&p_z,   g_z);
    cudaGetSymbolAddress((void**)&p_cs,  g_colsum);

    cudaFuncSetAttribute(qk_kernel<1>, cudaFuncAttributeMaxDynamicSharedMemorySize, QK_SMEM);
    cudaFuncSetAttribute(qk_kernel<2>, cudaFuncAttributeMaxDynamicSharedMemorySize, QK_SMEM);

    dim3 blk(256);

    // 0. zero z + colsum accumulators
    zero_kernel<<<(NBH * SEQ + 255) / 256, blk>>>(p_z, p_cs);

    // 1. qkv = x @ w_qkv
    gemm_nn<false><<<dim3(F3 / 128, BS / 128), blk>>>(
        x, w_qkv, p_qkv, HID, HID, F3, F3, 1.0f, nullptr);

    // 2. pass 1: Z[q] = sum_k exp(q.k/8)
    qk_kernel<1><<<dim3(SEQ / 128, SEQ / 128, NBH), blk, QK_SMEM>>>(p_qkv, p_z, nullptr);

    // 3. pass 2: colsum[k] = sum_q exp(q.k/8)/Z[q]
    qk_kernel<2><<<dim3(SEQ / 128, SEQ / 128, NBH), blk, QK_SMEM>>>(p_qkv, p_z, p_cs);

    // 4. out = (v * colsum) @ w_o   (scale fused into A-load)
    gemm_nn<true><<<dim3(HID / 128, BS / 128), blk>>>(
        p_qkv + 2 * HID, w_o, out, HID, F3, HID, HID, 1.0f, p_cs);
}